// round 15
// baseline (speedup 1.0000x reference)
#include <cuda_runtime.h>

#define GH 96
#define GW 96
#define HW (GH*GW)
#define BSZ 8
#define LN 16
#define PN 16
#define NCELL (BSZ*GH*GW)   /* 73728 */
#define TPB 256
#define CPB 64              /* cells per block: 4 threads per cell (line-split) */
#define NBLK (NCELL/CPB)    /* 1152 */

__device__ float g_partials[NBLK];
__device__ unsigned int g_ticket;   // zero-init; last block resets it

typedef unsigned long long u64;

__device__ __forceinline__ float asqrt(float x) {
    float r;
    asm("sqrt.approx.f32 %0, %1;" : "=f"(r) : "f"(x));
    return r;
}
__device__ __forceinline__ float arcp(float x) {
    float r;
    asm("rcp.approx.f32 %0, %1;" : "=f"(r) : "f"(x));
    return r;
}
__device__ __forceinline__ u64 pk2(float a, float b) {
    u64 r; asm("mov.b64 %0, {%1, %2};" : "=l"(r) : "f"(a), "f"(b)); return r;
}
__device__ __forceinline__ void upk2(float& a, float& b, u64 v) {
    asm("mov.b64 {%0, %1}, %2;" : "=f"(a), "=f"(b) : "l"(v));
}
__device__ __forceinline__ u64 add2(u64 a, u64 b) {
    u64 r; asm("add.rn.f32x2 %0, %1, %2;" : "=l"(r) : "l"(a), "l"(b)); return r;
}
__device__ __forceinline__ u64 mul2(u64 a, u64 b) {
    u64 r; asm("mul.rn.f32x2 %0, %1, %2;" : "=l"(r) : "l"(a), "l"(b)); return r;
}
__device__ __forceinline__ u64 fma2(u64 a, u64 b, u64 c) {
    u64 r; asm("fma.rn.f32x2 %0, %1, %2, %3;" : "=l"(r) : "l"(a), "l"(b), "l"(c)); return r;
}

__global__ __launch_bounds__(TPB, 4)
void yolino_main(const float* __restrict__ target, const float* __restrict__ pred,
                 float* __restrict__ out)
{
    // Mapping: g = lane&3 selects this thread's 4 lines; cb = tid>>2 is the
    // cell within the block. Cell partners are lanes (xor 1, xor 2) — same warp.
    const int tid = threadIdx.x;
    const int g   = tid & 3;
    const int cb  = tid >> 2;
    const int n   = blockIdx.x * CPB + cb;   // grid cell

    const int w  = n % GW;
    const int t1 = n / GW;
    const int h  = t1 % GH;
    const int b  = t1 / GH;

    const int cell_off = h * GW + w;
    const float* tb = target + b * (64 * HW) + (g * 16) * HW + cell_off;
    const float* pb = pred   + b * (96 * HW) + cell_off;

    // This thread's 4 lines, packed endpoint pairs: tx=(x1,x2), ty=(y1,y2).
    u64 tx[4], ty[4];
    unsigned tmask = 0;
    #pragma unroll
    for (int l = 0; l < 4; ++l) {
        float x1 = tb[(l * 4 + 0) * HW];
        float y1 = tb[(l * 4 + 1) * HW];
        float x2 = tb[(l * 4 + 2) * HW];
        float y2 = tb[(l * 4 + 3) * HW];
        tx[l] = pk2(x1, x2);
        ty[l] = pk2(y1, y2);
        float s = (x1 + y1) + (x2 + y2);
        if (s > 0.f) tmask |= (1u << l);
    }

    float mt[PN];     // per-p local min of e over this thread's 4 lines
    u64   cpk = 0;    // per-p local tie count (4 bits per p)

    // Prefetch predictor 0's coordinate channels (conf/cls not needed in loop).
    float q0 = pb[0], q1 = pb[HW], q2 = pb[2 * HW], q3 = pb[3 * HW];

    // Hot loop: NO cross-thread communication. Fully unrolled so mt[] stays
    // in registers.
    #pragma unroll
    for (int p = 0; p < PN; ++p) {
        const float c0 = q0, c1 = q1, c2 = q2, c3 = q3;

        if (p + 1 < PN) {
            const float* nb = pb + (p + 1) * (6 * HW);
            q0 = nb[0]; q1 = nb[HW]; q2 = nb[2 * HW]; q3 = nb[3 * HW];
        }

        const u64 ncx = pk2(-c0, -c2);
        const u64 ncy = pk2(-c1, -c3);

        // e[l] = d^2 = s1 + s2 + 2*sqrt(s1*s2): one sqrt per line.
        float e[4];
        #pragma unroll
        for (int l = 0; l < 4; ++l) {
            u64 dx = add2(tx[l], ncx);
            u64 dy = add2(ty[l], ncy);
            u64 s  = fma2(dx, dx, mul2(dy, dy));
            float s1, s2;
            upk2(s1, s2, s);
            e[l] = fmaf(2.f, asqrt(s1 * s2), s1 + s2);
        }

        // Local min over 4 lines (depth-2 tree).
        const float m = fminf(fminf(e[0], e[1]), fminf(e[2], e[3]));
        mt[p] = m;

        // Local tie count at the local min, masked by valid lines.
        int cnt = 0;
        cnt += (e[0] == m && (tmask & 1u)) ? 1 : 0;
        cnt += (e[1] == m && (tmask & 2u)) ? 1 : 0;
        cnt += (e[2] == m && (tmask & 4u)) ? 1 : 0;
        cnt += (e[3] == m && (tmask & 8u)) ? 1 : 0;
        cpk |= (u64)cnt << (4 * p);
    }

    // Epilogue: one communication pass per predictor (outside the hot loop).
    // All 4 partner threads end with identical terms -> scale by 1/4 at the end.
    float loss = 0.f;
    #pragma unroll
    for (int p = 0; p < PN; ++p) {
        // Global min of e across the cell's 16 lines (bit-exact: identical
        // instruction sequences produce identical e on every thread).
        float m = mt[p];
        m = fminf(m, __shfl_xor_sync(0xffffffffu, m, 1));
        m = fminf(m, __shfl_xor_sync(0xffffffffu, m, 2));

        // This thread's ties count only if its local min IS the global min.
        int myc = (int)((cpk >> (4 * p)) & 15u);
        myc = (mt[p] == m) ? myc : 0;
        myc += __shfl_xor_sync(0xffffffffu, myc, 1);
        myc += __shfl_xor_sync(0xffffffffu, myc, 2);

        // Recover min distance; gate at 2 (thr=-1 selects nothing otherwise).
        const float md  = asqrt(m);
        const float cnt = (md < 2.f) ? (float)myc : 0.f;

        loss = fmaf(md, cnt, loss);                    // dist term

        const float c4 = pb[(6 * p + 4) * HW];
        const float c5 = pb[(6 * p + 5) * HW];
        float sig = arcp(1.f + __expf(-c4));           // sigmoid(conf)
        float ee  = (cnt > 0.f) ? (sig - 1.f) : sig;
        loss = fmaf(ee, ee, loss);                     // conf term

        if (!(c5 > 0.f)) loss += cnt;                  // cls term
    }

    // ---- block reduction (deterministic) ----
    #pragma unroll
    for (int o = 16; o > 0; o >>= 1)
        loss += __shfl_xor_sync(0xffffffffu, loss, o);

    __shared__ float sw[TPB / 32];
    __shared__ bool  s_last;
    const int lane = tid & 31;
    const int wid  = tid >> 5;
    if (lane == 0) sw[wid] = loss;
    __syncthreads();
    if (wid == 0) {
        float v = (lane < TPB / 32) ? sw[lane] : 0.f;
        #pragma unroll
        for (int o = 4; o > 0; o >>= 1)
            v += __shfl_xor_sync(0xffffffffu, v, o);
        if (lane == 0) {
            g_partials[blockIdx.x] = v;
            __threadfence();
            unsigned t = atomicAdd(&g_ticket, 1u);
            s_last = (t == NBLK - 1);
        }
    }
    __syncthreads();

    // ---- last block folds all partials into the output ----
    if (s_last) {
        __threadfence();  // acquire: make all g_partials visible
        const int t = tid;
        float v = 0.f;
        for (int i = t; i < NBLK; i += TPB)   // fixed order: deterministic
            v += g_partials[i];
        __shared__ float s[TPB];
        s[t] = v;
        __syncthreads();
        #pragma unroll
        for (int o = TPB / 2; o > 0; o >>= 1) {
            if (t < o) s[t] += s[t + o];
            __syncthreads();
        }
        if (t == 0) {
            // Every (cell,p) term was accumulated by all 4 partner threads.
            out[0] = s[0] * (1.0f / (4.0f * BSZ));
            g_ticket = 0;   // reset for the next (graph-replayed) launch
        }
    }
}

extern "C" void kernel_launch(void* const* d_in, const int* in_sizes, int n_in,
                              void* d_out, int out_size)
{
    const float* target = (const float*)d_in[0];
    const float* pred   = (const float*)d_in[1];
    float* out = (float*)d_out;

    yolino_main<<<NBLK, TPB>>>(target, pred, out);
}

// round 16
// speedup vs baseline: 1.3034x; 1.3034x over previous
#include <cuda_runtime.h>

#define GH 96
#define GW 96
#define HW (GH*GW)
#define BSZ 8
#define LN 16
#define PN 16
#define NCELL (BSZ*GH*GW)   /* 73728 */
#define TPB 128
#define NBLK (NCELL/TPB)    /* 576 */

__device__ float g_partials[NBLK];
__device__ unsigned int g_ticket;   // zero-init; last block resets it

typedef unsigned long long u64;

__device__ __forceinline__ float asqrt(float x) {
    float r;
    asm("sqrt.approx.f32 %0, %1;" : "=f"(r) : "f"(x));
    return r;
}
__device__ __forceinline__ float arcp(float x) {
    float r;
    asm("rcp.approx.f32 %0, %1;" : "=f"(r) : "f"(x));
    return r;
}
__device__ __forceinline__ u64 pk2(float a, float b) {
    u64 r; asm("mov.b64 %0, {%1, %2};" : "=l"(r) : "f"(a), "f"(b)); return r;
}
__device__ __forceinline__ void upk2(float& a, float& b, u64 v) {
    asm("mov.b64 {%0, %1}, %2;" : "=f"(a), "=f"(b) : "l"(v));
}
__device__ __forceinline__ u64 add2(u64 a, u64 b) {
    u64 r; asm("add.rn.f32x2 %0, %1, %2;" : "=l"(r) : "l"(a), "l"(b)); return r;
}
__device__ __forceinline__ u64 mul2(u64 a, u64 b) {
    u64 r; asm("mul.rn.f32x2 %0, %1, %2;" : "=l"(r) : "l"(a), "l"(b)); return r;
}
__device__ __forceinline__ u64 fma2(u64 a, u64 b, u64 c) {
    u64 r; asm("fma.rn.f32x2 %0, %1, %2, %3;" : "=l"(r) : "l"(a), "l"(b), "l"(c)); return r;
}

__global__ __launch_bounds__(TPB, 4)
void yolino_main(const float* __restrict__ target, const float* __restrict__ pred,
                 float* __restrict__ out)
{
    const int n = blockIdx.x * TPB + threadIdx.x;   // n in [0, NCELL)
    const int w  = n % GW;
    const int t1 = n / GW;
    const int h  = t1 % GH;
    const int b  = t1 / GH;

    const float* tb = target + b * (64 * HW) + h * GW + w;
    const float* pb = pred   + b * (96 * HW) + h * GW + w;

    // Target lines packed ACROSS LINE PAIRS: for pair lp = (2lp, 2lp+1),
    // tx1[lp]=(x1_a,x1_b), ty1=(y1_a,y1_b), tx2=(x2_a,x2_b), ty2=(y2_a,y2_b).
    u64 tx1[LN/2], ty1[LN/2], tx2[LN/2], ty2[LN/2];
    unsigned tmask = 0;
    #pragma unroll
    for (int lp = 0; lp < LN / 2; ++lp) {
        float xa1 = tb[(8 * lp + 0) * HW];
        float ya1 = tb[(8 * lp + 1) * HW];
        float xa2 = tb[(8 * lp + 2) * HW];
        float ya2 = tb[(8 * lp + 3) * HW];
        float xb1 = tb[(8 * lp + 4) * HW];
        float yb1 = tb[(8 * lp + 5) * HW];
        float xb2 = tb[(8 * lp + 6) * HW];
        float yb2 = tb[(8 * lp + 7) * HW];
        tx1[lp] = pk2(xa1, xb1);
        ty1[lp] = pk2(ya1, yb1);
        tx2[lp] = pk2(xa2, xb2);
        ty2[lp] = pk2(ya2, yb2);
        float sa = (xa1 + ya1) + (xa2 + ya2);
        float sb = (xb1 + yb1) + (xb2 + yb2);
        if (sa > 0.f) tmask |= (1u << (2 * lp));
        if (sb > 0.f) tmask |= (1u << (2 * lp + 1));
    }

    const u64 two2 = pk2(2.f, 2.f);

    float loss = 0.f;

    // Prefetch predictor 0's six channels.
    float q0 = pb[0], q1 = pb[HW], q2 = pb[2 * HW],
          q3 = pb[3 * HW], q4 = pb[4 * HW], q5 = pb[5 * HW];

    #pragma unroll 1
    for (int p = 0; p < PN; ++p) {
        const float c0 = q0, c1 = q1, c2 = q2, c3 = q3, c4 = q4, c5 = q5;

        // Prefetch next predictor while we crunch this one.
        if (p + 1 < PN) {
            const float* nb = pb + (p + 1) * (6 * HW);
            q0 = nb[0];      q1 = nb[HW];     q2 = nb[2 * HW];
            q3 = nb[3 * HW]; q4 = nb[4 * HW]; q5 = nb[5 * HW];
        }

        // Broadcast negated predictor coords (one per coordinate).
        const u64 nc0 = pk2(-c0, -c0), nc1 = pk2(-c1, -c1),
                  nc2 = pk2(-c2, -c2), nc3 = pk2(-c3, -c3);

        // Pass 1: per line-pair, fully packed through e = s1+s2+2*sqrt(s1*s2)
        // (monotone in d): 10 packed ops + 1 repack + 2 MUFU per 2 lines.
        float e[LN];
        #pragma unroll
        for (int lp = 0; lp < LN / 2; ++lp) {
            u64 dx1 = add2(tx1[lp], nc0);
            u64 dy1 = add2(ty1[lp], nc1);
            u64 dx2 = add2(tx2[lp], nc2);
            u64 dy2 = add2(ty2[lp], nc3);
            u64 s1  = fma2(dx1, dx1, mul2(dy1, dy1));   // (s1_a, s1_b)
            u64 s2  = fma2(dx2, dx2, mul2(dy2, dy2));   // (s2_a, s2_b)
            u64 sum = add2(s1, s2);                     // (s1+s2)
            u64 prd = mul2(s1, s2);                     // (s1*s2)
            float pa, pc;
            upk2(pa, pc, prd);
            u64 rp = pk2(asqrt(pa), asqrt(pc));         // (sqrt, sqrt)
            u64 e2 = fma2(two2, rp, sum);               // (e_a, e_b)
            upk2(e[2 * lp], e[2 * lp + 1], e2);          // free aliasing
        }

        // Pass 2: tree min over e (depth 4).
        float mm[8];
        #pragma unroll
        for (int i = 0; i < 8; ++i) mm[i] = fminf(e[2 * i], e[2 * i + 1]);
        #pragma unroll
        for (int i = 0; i < 4; ++i) mm[i] = fminf(mm[i], mm[i + 4]);
        mm[0] = fminf(mm[0], mm[2]);
        mm[1] = fminf(mm[1], mm[3]);
        const float me = fminf(mm[0], mm[1]);

        // Pass 3: tie mask on e (ties in e <=> ties in d).
        unsigned a0 = 0, a1 = 0;
        #pragma unroll
        for (int i = 0; i < 8; ++i) {
            a0 |= (e[i]     == me) ? (1u << i)       : 0u;
            a1 |= (e[i + 8] == me) ? (1u << (i + 8)) : 0u;
        }

        // Recover actual min distance (one sqrt per predictor).
        const float md = asqrt(me);

        // thr = (md<2) ? md : -1; distances >= 0 so thr=-1 selects nothing.
        const float cnt = (md < 2.f) ? (float)__popc((a0 | a1) & tmask) : 0.f;

        // dist term: selected entries all equal md.
        loss = fmaf(md, cnt, loss);

        // Confidence term: sig = 1/(1+exp(-c4)).
        float sig = arcp(1.f + __expf(-c4));
        float ee  = (cnt > 0.f) ? (sig - 1.f) : sig;
        loss = fmaf(ee, ee, loss);

        // Class term: cls_hard = 1 <=> c5 > 0.
        if (!(c5 > 0.f)) loss += cnt;
    }

    // ---- block reduction (deterministic) ----
    #pragma unroll
    for (int o = 16; o > 0; o >>= 1)
        loss += __shfl_xor_sync(0xffffffffu, loss, o);

    __shared__ float sw[TPB / 32];
    __shared__ bool  s_last;
    const int lane = threadIdx.x & 31;
    const int wid  = threadIdx.x >> 5;
    if (lane == 0) sw[wid] = loss;
    __syncthreads();
    if (wid == 0) {
        float v = (lane < TPB / 32) ? sw[lane] : 0.f;
        #pragma unroll
        for (int o = 2; o > 0; o >>= 1)
            v += __shfl_xor_sync(0xffffffffu, v, o);
        if (lane == 0) {
            g_partials[blockIdx.x] = v;
            __threadfence();
            unsigned t = atomicAdd(&g_ticket, 1u);
            s_last = (t == NBLK - 1);
        }
    }
    __syncthreads();

    // ---- last block folds all partials into the output ----
    if (s_last) {
        __threadfence();  // acquire: make all g_partials visible
        const int t = threadIdx.x;
        float v = 0.f;
        for (int i = t; i < NBLK; i += TPB)   // fixed order: deterministic
            v += g_partials[i];
        __shared__ float s[TPB];
        s[t] = v;
        __syncthreads();
        #pragma unroll
        for (int o = TPB / 2; o > 0; o >>= 1) {
            if (t < o) s[t] += s[t + o];
            __syncthreads();
        }
        if (t == 0) {
            out[0] = s[0] * (1.0f / BSZ);
            g_ticket = 0;   // reset for the next (graph-replayed) launch
        }
    }
}

extern "C" void kernel_launch(void* const* d_in, const int* in_sizes, int n_in,
                              void* d_out, int out_size)
{
    const float* target = (const float*)d_in[0];
    const float* pred   = (const float*)d_in[1];
    float* out = (float*)d_out;

    yolino_main<<<NBLK, TPB>>>(target, pred, out);
}

// round 17
// speedup vs baseline: 1.3053x; 1.0015x over previous
#include <cuda_runtime.h>

#define GH 96
#define GW 96
#define HW (GH*GW)
#define BSZ 8
#define LN 16
#define PN 16
#define NCELL (BSZ*GH*GW)   /* 73728 */
#define TPB 128
#define NBLK (NCELL/TPB)    /* 576 */

__device__ float g_partials[NBLK];
__device__ unsigned int g_ticket;   // zero-init; last block resets it

typedef unsigned long long u64;

__device__ __forceinline__ float asqrt(float x) {
    float r;
    asm("sqrt.approx.f32 %0, %1;" : "=f"(r) : "f"(x));
    return r;
}
__device__ __forceinline__ float arcp(float x) {
    float r;
    asm("rcp.approx.f32 %0, %1;" : "=f"(r) : "f"(x));
    return r;
}
__device__ __forceinline__ u64 pk2(float a, float b) {
    u64 r; asm("mov.b64 %0, {%1, %2};" : "=l"(r) : "f"(a), "f"(b)); return r;
}
__device__ __forceinline__ void upk2(float& a, float& b, u64 v) {
    asm("mov.b64 {%0, %1}, %2;" : "=f"(a), "=f"(b) : "l"(v));
}
__device__ __forceinline__ u64 add2(u64 a, u64 b) {
    u64 r; asm("add.rn.f32x2 %0, %1, %2;" : "=l"(r) : "l"(a), "l"(b)); return r;
}
__device__ __forceinline__ u64 mul2(u64 a, u64 b) {
    u64 r; asm("mul.rn.f32x2 %0, %1, %2;" : "=l"(r) : "l"(a), "l"(b)); return r;
}
__device__ __forceinline__ u64 fma2(u64 a, u64 b, u64 c) {
    u64 r; asm("fma.rn.f32x2 %0, %1, %2, %3;" : "=l"(r) : "l"(a), "l"(b), "l"(c)); return r;
}

__global__ __launch_bounds__(TPB, 4)
void yolino_main(const float* __restrict__ target, const float* __restrict__ pred,
                 float* __restrict__ out)
{
    const int n = blockIdx.x * TPB + threadIdx.x;   // n in [0, NCELL)
    const int w  = n % GW;
    const int t1 = n / GW;
    const int h  = t1 % GH;
    const int b  = t1 / GH;

    const float* tb = target + b * (64 * HW) + h * GW + w;
    const float* pb = pred   + b * (96 * HW) + h * GW + w;

    // Target lines packed ACROSS LINE PAIRS: for pair lp = (2lp, 2lp+1),
    // tx1[lp]=(x1_a,x1_b), ty1=(y1_a,y1_b), tx2=(x2_a,x2_b), ty2=(y2_a,y2_b).
    u64 tx1[LN/2], ty1[LN/2], tx2[LN/2], ty2[LN/2];
    unsigned tmask = 0;
    #pragma unroll
    for (int lp = 0; lp < LN / 2; ++lp) {
        float xa1 = tb[(8 * lp + 0) * HW];
        float ya1 = tb[(8 * lp + 1) * HW];
        float xa2 = tb[(8 * lp + 2) * HW];
        float ya2 = tb[(8 * lp + 3) * HW];
        float xb1 = tb[(8 * lp + 4) * HW];
        float yb1 = tb[(8 * lp + 5) * HW];
        float xb2 = tb[(8 * lp + 6) * HW];
        float yb2 = tb[(8 * lp + 7) * HW];
        tx1[lp] = pk2(xa1, xb1);
        ty1[lp] = pk2(ya1, yb1);
        tx2[lp] = pk2(xa2, xb2);
        ty2[lp] = pk2(ya2, yb2);
        float sa = (xa1 + ya1) + (xa2 + ya2);
        float sb = (xb1 + yb1) + (xb2 + yb2);
        if (sa > 0.f) tmask |= (1u << (2 * lp));
        if (sb > 0.f) tmask |= (1u << (2 * lp + 1));
    }

    const u64 two2 = pk2(2.f, 2.f);

    float loss = 0.f;

    // Prefetch predictor 0; pp is a single strided pointer -> constant-offset
    // LDGs in the loop (kills per-iteration IMAD address math).
    const float* pp = pb;
    float q0 = pp[0], q1 = pp[HW], q2 = pp[2 * HW],
          q3 = pp[3 * HW], q4 = pp[4 * HW], q5 = pp[5 * HW];

    #pragma unroll 1
    for (int p = 0; p < PN; ++p) {
        const float c0 = q0, c1 = q1, c2 = q2, c3 = q3, c4 = q4, c5 = q5;

        // Prefetch next predictor (single pointer bump, imm-offset loads).
        pp += 6 * HW;
        if (p + 1 < PN) {
            q0 = pp[0];      q1 = pp[HW];     q2 = pp[2 * HW];
            q3 = pp[3 * HW]; q4 = pp[4 * HW]; q5 = pp[5 * HW];
        }

        // Broadcast negated predictor coords (one per coordinate).
        const u64 nc0 = pk2(-c0, -c0), nc1 = pk2(-c1, -c1),
                  nc2 = pk2(-c2, -c2), nc3 = pk2(-c3, -c3);

        // Pass 1: per line-pair, fully packed through e = s1+s2+2*sqrt(s1*s2)
        // (monotone in d): 10 packed ops + 1 repack + 2 MUFU per 2 lines.
        float e[LN];
        #pragma unroll
        for (int lp = 0; lp < LN / 2; ++lp) {
            u64 dx1 = add2(tx1[lp], nc0);
            u64 dy1 = add2(ty1[lp], nc1);
            u64 dx2 = add2(tx2[lp], nc2);
            u64 dy2 = add2(ty2[lp], nc3);
            u64 s1  = fma2(dx1, dx1, mul2(dy1, dy1));   // (s1_a, s1_b)
            u64 s2  = fma2(dx2, dx2, mul2(dy2, dy2));   // (s2_a, s2_b)
            u64 sum = add2(s1, s2);                     // (s1+s2)
            u64 prd = mul2(s1, s2);                     // (s1*s2)
            float pa, pc;
            upk2(pa, pc, prd);
            u64 rp = pk2(asqrt(pa), asqrt(pc));         // (sqrt, sqrt)
            u64 e2 = fma2(two2, rp, sum);               // (e_a, e_b)
            upk2(e[2 * lp], e[2 * lp + 1], e2);          // free aliasing
        }

        // Pass 2: tree min over e (depth 4).
        float mm[8];
        #pragma unroll
        for (int i = 0; i < 8; ++i) mm[i] = fminf(e[2 * i], e[2 * i + 1]);
        #pragma unroll
        for (int i = 0; i < 4; ++i) mm[i] = fminf(mm[i], mm[i + 4]);
        mm[0] = fminf(mm[0], mm[2]);
        mm[1] = fminf(mm[1], mm[3]);
        const float me = fminf(mm[0], mm[1]);

        // Pass 3: tie mask on e (ties in e <=> ties in d).
        unsigned a0 = 0, a1 = 0;
        #pragma unroll
        for (int i = 0; i < 8; ++i) {
            a0 |= (e[i]     == me) ? (1u << i)       : 0u;
            a1 |= (e[i + 8] == me) ? (1u << (i + 8)) : 0u;
        }

        // Recover actual min distance (one sqrt per predictor).
        const float md = asqrt(me);

        // thr = (md<2) ? md : -1; distances >= 0 so thr=-1 selects nothing.
        const float cnt = (md < 2.f) ? (float)__popc((a0 | a1) & tmask) : 0.f;

        // dist term: selected entries all equal md.
        loss = fmaf(md, cnt, loss);

        // Confidence term: sig = 1/(1+exp(-c4)).
        float sig = arcp(1.f + __expf(-c4));
        float ee  = (cnt > 0.f) ? (sig - 1.f) : sig;
        loss = fmaf(ee, ee, loss);

        // Class term: cls_hard = 1 <=> c5 > 0.
        if (!(c5 > 0.f)) loss += cnt;
    }

    // ---- block reduction (deterministic) ----
    #pragma unroll
    for (int o = 16; o > 0; o >>= 1)
        loss += __shfl_xor_sync(0xffffffffu, loss, o);

    __shared__ float sw[TPB / 32];
    __shared__ bool  s_last;
    const int lane = threadIdx.x & 31;
    const int wid  = threadIdx.x >> 5;
    if (lane == 0) sw[wid] = loss;
    __syncthreads();
    if (wid == 0) {
        float v = (lane < TPB / 32) ? sw[lane] : 0.f;
        #pragma unroll
        for (int o = 2; o > 0; o >>= 1)
            v += __shfl_xor_sync(0xffffffffu, v, o);
        if (lane == 0) {
            g_partials[blockIdx.x] = v;
            __threadfence();
            unsigned t = atomicAdd(&g_ticket, 1u);
            s_last = (t == NBLK - 1);
        }
    }
    __syncthreads();

    // ---- last block folds all partials into the output (shuffle tree) ----
    if (s_last) {
        __threadfence();  // acquire: make all g_partials visible
        const int t = threadIdx.x;
        float v = 0.f;
        for (int i = t; i < NBLK; i += TPB)   // fixed order: deterministic
            v += g_partials[i];
        #pragma unroll
        for (int o = 16; o > 0; o >>= 1)
            v += __shfl_xor_sync(0xffffffffu, v, o);
        __shared__ float sr[TPB / 32];
        if (lane == 0) sr[wid] = v;
        __syncthreads();
        if (t == 0) {
            float r = sr[0] + sr[1] + sr[2] + sr[3];
            out[0] = r * (1.0f / BSZ);
            g_ticket = 0;   // reset for the next (graph-replayed) launch
        }
    }
}

extern "C" void kernel_launch(void* const* d_in, const int* in_sizes, int n_in,
                              void* d_out, int out_size)
{
    const float* target = (const float*)d_in[0];
    const float* pred   = (const float*)d_in[1];
    float* out = (float*)d_out;

    yolino_main<<<NBLK, TPB>>>(target, pred, out);
}